// round 1
// baseline (speedup 1.0000x reference)
#include <cuda_runtime.h>
#include <cuda_bf16.h>

#define Bn 16
#define Sn 512
#define Tn 16
#define Pn 4
#define Gn 128                 // Sn / Pn
#define NPATCH (Bn * Gn * Gn)  // 262144

// Intermediate normalized CAM, layout [b, gy, gx, t] (t contiguous) — 16 MB scratch.
__device__ float g_top[(size_t)NPATCH * Tn];

// ---------------------------------------------------------------------------
// Kernel 1: per-patch c[t] = sum_k input[b, gy*4+py, gx*4+px, t] * W[n, k, 0]
// then (c - min_t) / (max_t - min_t). 16 threads per patch (one per t).
// ---------------------------------------------------------------------------
__global__ void __launch_bounds__(256)
patch_cam_kernel(const float* __restrict__ input, const float* __restrict__ w3)
{
    int tid = blockIdx.x * blockDim.x + threadIdx.x;
    int t = tid & 15;
    int n = tid >> 4;                 // patch index: ((b*G)+gy)*G + gx
    int gx = n & (Gn - 1);
    int gy = (n >> 7) & (Gn - 1);
    int b  = n >> 14;

    // Thread t loads W[n, k=t, m=0] (stride 6 floats); broadcast via shfl below.
    float w = __ldg(&w3[n * (Pn * Pn * 6) + t * 6]);

    const float* base = input + (((size_t)b * Sn + gy * Pn) * Sn + gx * Pn) * Tn + t;

    int lane = threadIdx.x & 31;
    unsigned grp = (unsigned)(lane & 16);   // which 16-lane half of the warp

    float acc = 0.0f;
    #pragma unroll
    for (int k = 0; k < 16; ++k) {
        float wk = __shfl_sync(0xffffffffu, w, (int)(grp | (unsigned)k));
        int py = k >> 2;
        int px = k & 3;
        acc = fmaf(base[((size_t)py * Sn + px) * Tn], wk, acc);
    }

    // min / max over the 16 t-lanes of this patch (xor 8,4,2,1 stays in-group)
    float mn = acc, mx = acc;
    #pragma unroll
    for (int o = 8; o >= 1; o >>= 1) {
        mn = fminf(mn, __shfl_xor_sync(0xffffffffu, mn, o));
        mx = fmaxf(mx, __shfl_xor_sync(0xffffffffu, mx, o));
    }

    g_top[(size_t)n * Tn + t] = (acc - mn) / (mx - mn);
}

// ---------------------------------------------------------------------------
// Kernel 2: bilinear upsample (g,g) -> (s,s), align_corners=True.
// One thread per (b, y, x); blends 4 neighbor 16-float vectors via float4.
// Output layout: out[(b*S + y)*S + x, t], t contiguous.
// ---------------------------------------------------------------------------
__global__ void __launch_bounds__(256)
upsample_kernel(float* __restrict__ out)
{
    int idx = blockIdx.x * blockDim.x + threadIdx.x;   // (b, y, x) flattened
    int x = idx & (Sn - 1);
    int y = (idx >> 9) & (Sn - 1);
    int b = idx >> 18;

    const float r = (float)((double)(Gn - 1) / (double)(Sn - 1));
    float cy = (float)y * r;
    float cx = (float)x * r;
    int i0 = min((int)cy, Gn - 2);
    int j0 = min((int)cx, Gn - 2);
    float wy = cy - (float)i0;
    float wx = cx - (float)j0;

    const float4* p00 = (const float4*)&g_top[(((size_t)b * Gn + i0) * Gn + j0) * Tn];
    const float4* p10 = (const float4*)&g_top[(((size_t)b * Gn + i0 + 1) * Gn + j0) * Tn];
    const float4* p01 = p00 + 4;   // j0+1 : +16 floats
    const float4* p11 = p10 + 4;

    float w00 = (1.0f - wy) * (1.0f - wx);
    float w01 = (1.0f - wy) * wx;
    float w10 = wy * (1.0f - wx);
    float w11 = wy * wx;

    float4* o = (float4*)(out + (size_t)idx * Tn);
    #pragma unroll
    for (int q = 0; q < 4; ++q) {
        float4 a = p00[q], c = p01[q], d = p10[q], e = p11[q];
        float4 v;
        v.x = w00 * a.x + w01 * c.x + w10 * d.x + w11 * e.x;
        v.y = w00 * a.y + w01 * c.y + w10 * d.y + w11 * e.y;
        v.z = w00 * a.z + w01 * c.z + w10 * d.z + w11 * e.z;
        v.w = w00 * a.w + w01 * c.w + w10 * d.w + w11 * e.w;
        o[q] = v;
    }
}

extern "C" void kernel_launch(void* const* d_in, const int* in_sizes, int n_in,
                              void* d_out, int out_size)
{
    const float* input = (const float*)d_in[0];   // (16,512,512,16) f32
    const float* w3    = (const float*)d_in[1];   // (262144,16,6)  f32
    float* out = (float*)d_out;                   // (16*512*512, 16) f32

    // Kernel 1: NPATCH * 16 threads
    {
        int total = NPATCH * Tn;                  // 4,194,304
        patch_cam_kernel<<<total / 256, 256>>>(input, w3);
    }
    // Kernel 2: B*S*S threads
    {
        int total = Bn * Sn * Sn;                 // 4,194,304
        upsample_kernel<<<total / 256, 256>>>(out);
    }
    (void)in_sizes; (void)n_in; (void)out_size;
}